// round 13
// baseline (speedup 1.0000x reference)
#include <cuda_runtime.h>
#include <cuda_bf16.h>

// Problem constants (fixed by the reference)
#define BB  4
#define LL  512
#define HH  768
#define SS  100
#define RR  100
#define EE  25
#define NEC 10              // entity classes
#define NRC 6               // relation classes
#define NEGV (-1e20f)

#define H4       (HH/4)         // 192 float4 lanes per hidden row
#define SPAN_DIM (HH + EE)      // 793
#define REL_DIM  (3*HH + 2*EE)  // 2354
#define NENT     (BB*SS)        // 400
#define NREL     (BB*RR)        // 400

static __device__ __forceinline__ float4 fmax4(float4 a, float4 b) {
    a.x = fmaxf(a.x, b.x); a.y = fmaxf(a.y, b.y);
    a.z = fmaxf(a.z, b.z); a.w = fmaxf(a.w, b.w);
    return a;
}

// masked max pool over a contiguous span, this thread's float4 lane
static __device__ __forceinline__
float4 pool_span(const float4* __restrict__ hb, int start, int len)
{
    float4 mx = make_float4(NEGV, NEGV, NEGV, NEGV);
    int l = start;
    const int e = start + len;
    for (; l + 4 <= e; l += 4) {
        float4 v0 = hb[(size_t)(l+0) * H4];
        float4 v1 = hb[(size_t)(l+1) * H4];
        float4 v2 = hb[(size_t)(l+2) * H4];
        float4 v3 = hb[(size_t)(l+3) * H4];
        mx = fmax4(mx, fmax4(fmax4(v0, v1), fmax4(v2, v3)));
    }
    for (; l < e; ++l)
        mx = fmax4(mx, hb[(size_t)l * H4]);
    return mx;
}

// -----------------------------------------------------------------------------
// Single kernel, 800 fully independent blocks:
//   blocks [0,400):   entity  — scan + pool + size emb + w_span dot -> entity logits
//   blocks [400,800): relation — scan 3 masks + INTERLEAVED 3-span pool + w_rel dot
// -----------------------------------------------------------------------------
__global__ void __launch_bounds__(256)
spert_onekernel(const float* __restrict__ hid,
                const int*   __restrict__ emask,
                const int*   __restrict__ rel,
                const int*   __restrict__ cmask,
                const float* __restrict__ size_emb,
                const float* __restrict__ w_span,
                const float* __restrict__ b_span,
                const float* __restrict__ w_rel,
                const float* __restrict__ b_rel,
                float*       __restrict__ out)
{
    __shared__ float sred[8][NEC];
    __shared__ int s_start[3];
    __shared__ int s_len[3];

    const int bid  = blockIdx.x;
    const int t    = threadIdx.x;
    const int warp = t >> 5, lane = t & 31;

    if (bid < NENT) {
        // ================= ENTITY BLOCK (unchanged from R12) =================
        const int idx = bid;                 // b*S + s
        const int b   = idx / SS;

        const int* mrow = emask + (size_t)idx * LL;
        const int m0 = mrow[t];
        const int m1 = mrow[t + 256];
        if (t == 0) { s_start[0] = LL; s_len[0] = 0; }
        __syncthreads();
        {
            unsigned b0 = __ballot_sync(0xffffffffu, m0 != 0);
            unsigned b1 = __ballot_sync(0xffffffffu, m1 != 0);
            if (lane == 0) {
                int st = LL, cnt = __popc(b0) + __popc(b1);
                if (b0) st = (warp << 5) + __ffs(b0) - 1;
                else if (b1) st = 256 + (warp << 5) + __ffs(b1) - 1;
                if (cnt) { atomicMin(&s_start[0], st); atomicAdd(&s_len[0], cnt); }
            }
        }
        __syncthreads();
        const int start = s_start[0];
        const int len   = s_len[0];

        float rv[4] = {0.f, 0.f, 0.f, 0.f};
        if (t < H4) {
            const float4* hb = reinterpret_cast<const float4*>(hid + (size_t)b * LL * HH) + t;
            float4 mx = pool_span(hb, start, len);
            rv[0] = mx.x; rv[1] = mx.y; rv[2] = mx.z; rv[3] = mx.w;
        } else if (t < 199) {                // rows 768..795 -> size dims 0..27
            const int k = 4*t - HH;
            const float* se = size_emb + len * EE;
            #pragma unroll
            for (int q = 0; q < 4; ++q)
                rv[q] = (k + q < EE) ? se[k + q] : 0.f;
        }

        float acc[NEC];
        #pragma unroll
        for (int j = 0; j < NEC; ++j) acc[j] = 0.f;
        if (t < 198) {                       // rows 4t+3 <= 791 < 793
            float w40[40];
            const float4* wp = reinterpret_cast<const float4*>(w_span + 40*t);
            #pragma unroll
            for (int q = 0; q < 10; ++q)
                *reinterpret_cast<float4*>(w40 + 4*q) = wp[q];
            #pragma unroll
            for (int r = 0; r < 4; ++r)
                #pragma unroll
                for (int j = 0; j < NEC; ++j)
                    acc[j] += rv[r] * w40[r*NEC + j];
        } else if (t == 198) {               // row 792 only
            #pragma unroll
            for (int j = 0; j < NEC; ++j)
                acc[j] = rv[0] * w_span[792*NEC + j];
        }

        #pragma unroll
        for (int j = 0; j < NEC; ++j) {
            float v = acc[j];
            #pragma unroll
            for (int o = 16; o; o >>= 1) v += __shfl_down_sync(0xffffffffu, v, o);
            if (lane == 0) sred[warp][j] = v;
        }
        __syncthreads();
        if (t < NEC) {
            float s = 0.f;
            #pragma unroll
            for (int w = 0; w < 8; ++w) s += sred[w][t];
            out[idx*NEC + t] = s + b_span[t];
        }
        return;
    }

    // ================= RELATION BLOCK =================
    const int idx = bid - NENT;              // b*R + r
    const int b   = idx / RR;

    // ctx mask is independent of rel -> issue first (1-hop scan chain)
    const int* crow = cmask + (size_t)idx * LL;
    const int c0 = crow[t], c1 = crow[t + 256];

    const int hi  = rel[idx*2 + 0];
    const int ti  = rel[idx*2 + 1];
    const int* hrow = emask + (size_t)(b*SS + hi) * LL;
    const int* trow = emask + (size_t)(b*SS + ti) * LL;
    const int h0 = hrow[t], h1 = hrow[t + 256];
    const int e0 = trow[t], e1 = trow[t + 256];

    if (t < 3) { s_start[t] = LL; s_len[t] = 0; }
    __syncthreads();
    {
        unsigned bc0 = __ballot_sync(0xffffffffu, c0 != 0);
        unsigned bc1 = __ballot_sync(0xffffffffu, c1 != 0);
        unsigned bh0 = __ballot_sync(0xffffffffu, h0 != 0);
        unsigned bh1 = __ballot_sync(0xffffffffu, h1 != 0);
        unsigned bt0 = __ballot_sync(0xffffffffu, e0 != 0);
        unsigned bt1 = __ballot_sync(0xffffffffu, e1 != 0);
        if (lane == 0) {
            int st, cnt;
            cnt = __popc(bc0) + __popc(bc1);
            if (cnt) {
                st = bc0 ? (warp << 5) + __ffs(bc0) - 1 : 256 + (warp << 5) + __ffs(bc1) - 1;
                atomicMin(&s_start[0], st); atomicAdd(&s_len[0], cnt);
            }
            cnt = __popc(bh0) + __popc(bh1);
            if (cnt) {
                st = bh0 ? (warp << 5) + __ffs(bh0) - 1 : 256 + (warp << 5) + __ffs(bh1) - 1;
                atomicMin(&s_start[1], st); atomicAdd(&s_len[1], cnt);
            }
            cnt = __popc(bt0) + __popc(bt1);
            if (cnt) {
                st = bt0 ? (warp << 5) + __ffs(bt0) - 1 : 256 + (warp << 5) + __ffs(bt1) - 1;
                atomicMin(&s_start[2], st); atomicAdd(&s_len[2], cnt);
            }
        }
    }
    __syncthreads();
    const int cst = s_start[0], clen = s_len[0];
    const int hst = s_start[1], hlen = s_len[1];
    const int tst = s_start[2], tlen = s_len[2];

    // ---- INTERLEAVED 3-span pool: 12 loads in flight per step, chain = 1 pool ----
    float rc[4] = {0,0,0,0}, rh[4] = {0,0,0,0}, rt[4] = {0,0,0,0};
    if (t < H4) {
        const float4* hb = reinterpret_cast<const float4*>(hid + (size_t)b * LL * HH) + t;
        float4 mc = make_float4(NEGV, NEGV, NEGV, NEGV);
        float4 mh = mc, mt = mc;
        const int ec  = cst + clen;
        const int ehh = hst + hlen;
        const int ett = tst + tlen;
        int gmax = clen > hlen ? clen : hlen;
        if (tlen > gmax) gmax = tlen;
        gmax = (gmax + 3) >> 2;
        int lc = cst, lh = hst, lt = tst;
        for (int g = 0; g < gmax; ++g) {
            #pragma unroll
            for (int q = 0; q < 4; ++q) {
                if (lc + q < ec)  mc = fmax4(mc, hb[(size_t)(lc + q) * H4]);
                if (lh + q < ehh) mh = fmax4(mh, hb[(size_t)(lh + q) * H4]);
                if (lt + q < ett) mt = fmax4(mt, hb[(size_t)(lt + q) * H4]);
            }
            lc += 4; lh += 4; lt += 4;
        }
        rc[0]=mc.x; rc[1]=mc.y; rc[2]=mc.z; rc[3]=mc.w;
        rh[0]=mh.x; rh[1]=mh.y; rh[2]=mh.z; rh[3]=mh.w;
        rt[0]=mt.x; rt[1]=mt.y; rt[2]=mt.z; rt[3]=mt.w;
    }

    float acc[NRC];
    #pragma unroll
    for (int j = 0; j < NRC; ++j) acc[j] = 0.f;

    if (t < H4) {
        // three weight regions, rows (region + 4t)..+3, contiguous 24 floats each
        float w24[24];
        #pragma unroll
        for (int g = 0; g < 3; ++g) {
            const float* rvv = (g == 0) ? rc : (g == 1) ? rh : rt;
            const int row0 = g*HH + 4*t;
            const float4* wp = reinterpret_cast<const float4*>(w_rel + row0*NRC);
            #pragma unroll
            for (int q = 0; q < 6; ++q)
                *reinterpret_cast<float4*>(w24 + 4*q) = wp[q];
            #pragma unroll
            for (int r = 0; r < 4; ++r)
                #pragma unroll
                for (int j = 0; j < NRC; ++j)
                    acc[j] += rvv[r] * w24[r*NRC + j];
        }
    } else if (t < 205) {
        // size dims: rows k..k+3, k = 2304 + 4*(t-192)
        const int k = 2304 + 4*(t - H4);
        const float* seh = size_emb + hlen * EE;
        const float* set = size_emb + tlen * EE;
        float rv[4];
        #pragma unroll
        for (int q = 0; q < 4; ++q) {
            const int d = (k + q) - 2304;            // 0..51
            rv[q] = (d < EE)     ? seh[d]
                  : (d < 2*EE)   ? set[d - EE]
                  : 0.f;
        }
        if (t < 204) {                               // rows k+3 <= 2351 < 2354
            float w24[24];
            const float4* wp = reinterpret_cast<const float4*>(w_rel + k*NRC);
            #pragma unroll
            for (int q = 0; q < 6; ++q)
                *reinterpret_cast<float4*>(w24 + 4*q) = wp[q];
            #pragma unroll
            for (int r = 0; r < 4; ++r)
                #pragma unroll
                for (int j = 0; j < NRC; ++j)
                    acc[j] += rv[r] * w24[r*NRC + j];
        } else {                                     // t==204: rows 2352,2353 only
            #pragma unroll
            for (int r = 0; r < 2; ++r)
                #pragma unroll
                for (int j = 0; j < NRC; ++j)
                    acc[j] += rv[r] * w_rel[(k + r)*NRC + j];
        }
    }

    #pragma unroll
    for (int j = 0; j < NRC; ++j) {
        float v = acc[j];
        #pragma unroll
        for (int o = 16; o; o >>= 1) v += __shfl_down_sync(0xffffffffu, v, o);
        if (lane == 0) sred[warp][j] = v;
    }
    __syncthreads();
    if (t < NRC) {
        float s = 0.f;
        #pragma unroll
        for (int w = 0; w < 8; ++w) s += sred[w][t];
        out[NENT*NEC + idx*NRC + t] = s + b_rel[t];
    }
}

// -----------------------------------------------------------------------------
// kernel_launch: inputs per metadata order:
//   0 hidden_states (f32)  1 entity_masks (i32)  2 relations (i32)
//   3 relation_context_masks (i32)  4 size_emb (f32)
//   5 w_span (f32)  6 b_span (f32)  7 w_rel (f32)  8 b_rel (f32)
// out: 6400 f32 = entity_logits (4000) ++ relation_logits (2400)
// -----------------------------------------------------------------------------
extern "C" void kernel_launch(void* const* d_in, const int* in_sizes, int n_in,
                              void* d_out, int out_size)
{
    const float* hid      = (const float*)d_in[0];
    const int*   emask    = (const int*)  d_in[1];
    const int*   rel      = (const int*)  d_in[2];
    const int*   cmask    = (const int*)  d_in[3];
    const float* size_emb = (const float*)d_in[4];
    const float* w_span   = (const float*)d_in[5];
    const float* b_span   = (const float*)d_in[6];
    const float* w_rel    = (const float*)d_in[7];
    const float* b_rel    = (const float*)d_in[8];
    float* out = (float*)d_out;

    spert_onekernel<<<NENT + NREL, 256>>>(hid, emask, rel, cmask, size_emb,
                                          w_span, b_span, w_rel, b_rel, out);
}

// round 14
// speedup vs baseline: 1.5844x; 1.5844x over previous
#include <cuda_runtime.h>
#include <cuda_bf16.h>

// Problem constants (fixed by the reference)
#define BB  4
#define LL  512
#define HH  768
#define SS  100
#define RR  100
#define EE  25
#define NEC 10              // entity classes
#define NRC 6               // relation classes
#define NEGV (-1e20f)

#define H4       (HH/4)         // 192 float4 lanes per hidden row
#define NENT     (BB*SS)        // 400
#define NREL     (BB*RR)        // 400
#define NROW     (NEC + 2*NRC)  // 22 projection rows per entity block

static __device__ __forceinline__ float4 fmax4(float4 a, float4 b) {
    a.x = fmaxf(a.x, b.x); a.y = fmaxf(a.y, b.y);
    a.z = fmaxf(a.z, b.z); a.w = fmaxf(a.w, b.w);
    return a;
}

// masked max pool over a contiguous span, this thread's float4 lane
static __device__ __forceinline__
float4 pool_span(const float4* __restrict__ hb, int start, int len)
{
    float4 mx = make_float4(NEGV, NEGV, NEGV, NEGV);
    int l = start;
    const int e = start + len;
    for (; l + 4 <= e; l += 4) {
        float4 v0 = hb[(size_t)(l+0) * H4];
        float4 v1 = hb[(size_t)(l+1) * H4];
        float4 v2 = hb[(size_t)(l+2) * H4];
        float4 v3 = hb[(size_t)(l+3) * H4];
        mx = fmax4(mx, fmax4(fmax4(v0, v1), fmax4(v2, v3)));
    }
    for (; l < e; ++l)
        mx = fmax4(mx, hb[(size_t)l * H4]);
    return mx;
}

// contiguous 0/1 span scan: (start,len) via ballot + shared atomics
static __device__ __forceinline__
void scan_span(const int* __restrict__ mrow, int t, int warp, int lane,
               int* s_start, int* s_len)
{
    const int m0 = mrow[t];
    const int m1 = mrow[t + 256];
    if (t == 0) { *s_start = LL; *s_len = 0; }
    __syncthreads();
    unsigned b0 = __ballot_sync(0xffffffffu, m0 != 0);
    unsigned b1 = __ballot_sync(0xffffffffu, m1 != 0);
    if (lane == 0) {
        int cnt = __popc(b0) + __popc(b1);
        if (cnt) {
            int st = b0 ? (warp << 5) + __ffs(b0) - 1
                        : 256 + (warp << 5) + __ffs(b1) - 1;
            atomicMin(s_start, st);
            atomicAdd(s_len, cnt);
        }
    }
    __syncthreads();
}

// per-entity projections (head/tail 6-vectors) — graph-safe static scratch
__device__ float g_p1[NENT*NRC];
__device__ float g_p2[NENT*NRC];

// -----------------------------------------------------------------------------
// K1: 400 entity blocks. Pool entity span; compute, in registers:
//   span logits (10) -> out, head proj (6) -> g_p1, tail proj (6) -> g_p2.
// Weights read directly: thread owning repr rows 4t..4t+3 loads the contiguous
// 40 floats of w_span and 24 floats of each w_rel slice (coalesced chunks).
// -----------------------------------------------------------------------------
__global__ void __launch_bounds__(256)
spert_entity_kernel(const float* __restrict__ hid,
                    const int*   __restrict__ emask,
                    const float* __restrict__ size_emb,
                    const float* __restrict__ w_span,
                    const float* __restrict__ b_span,
                    const float* __restrict__ w_rel,
                    float*       __restrict__ out)
{
    __shared__ float sred[8][NROW];
    __shared__ int s_start, s_len;

    const int idx  = blockIdx.x;         // b*S + s
    const int b    = idx / SS;
    const int t    = threadIdx.x;
    const int warp = t >> 5, lane = t & 31;

    scan_span(emask + (size_t)idx * LL, t, warp, lane, &s_start, &s_len);
    const int start = s_start;
    const int len   = s_len;

    float acc[NROW];
    #pragma unroll
    for (int r = 0; r < NROW; ++r) acc[r] = 0.f;

    if (t < H4) {
        // ---- pooled hidden dims 4t..4t+3 ----
        const float4* hb = reinterpret_cast<const float4*>(hid + (size_t)b * LL * HH) + t;
        const float4 mx = pool_span(hb, start, len);
        float rv[4] = {mx.x, mx.y, mx.z, mx.w};

        // span: w_span rows 4t..4t+3 (40 contiguous floats)
        {
            float w40[40];
            const float4* wp = reinterpret_cast<const float4*>(w_span + 40*t);
            #pragma unroll
            for (int q = 0; q < 10; ++q)
                *reinterpret_cast<float4*>(w40 + 4*q) = wp[q];
            #pragma unroll
            for (int r = 0; r < 4; ++r)
                #pragma unroll
                for (int j = 0; j < NEC; ++j)
                    acc[j] += rv[r] * w40[r*NEC + j];
        }
        // head: w_rel rows 768+4t (24 floats); tail: rows 1536+4t
        #pragma unroll
        for (int g = 0; g < 2; ++g) {
            float w24[24];
            const int row0 = (g + 1)*HH + 4*t;
            const float4* wp = reinterpret_cast<const float4*>(w_rel + row0*NRC);
            #pragma unroll
            for (int q = 0; q < 6; ++q)
                *reinterpret_cast<float4*>(w24 + 4*q) = wp[q];
            const int base = NEC + g*NRC;
            #pragma unroll
            for (int r = 0; r < 4; ++r)
                #pragma unroll
                for (int j = 0; j < NRC; ++j)
                    acc[base + j] += rv[r] * w24[r*NRC + j];
        }
    } else if (t < 199) {
        // ---- size-embedding dims d = 4t-768 .. +3 (valid d < 25), scalar path ----
        const int d0 = 4*t - HH;
        const float* se = size_emb + len * EE;
        #pragma unroll
        for (int q = 0; q < 4; ++q) {
            const int d = d0 + q;
            if (d < EE) {
                const float sv = se[d];
                #pragma unroll
                for (int j = 0; j < NEC; ++j)
                    acc[j] += sv * w_span[(HH + d)*NEC + j];
                #pragma unroll
                for (int j = 0; j < NRC; ++j) {
                    acc[NEC + j]       += sv * w_rel[(3*HH + d)*NRC + j];
                    acc[NEC + NRC + j] += sv * w_rel[(3*HH + EE + d)*NRC + j];
                }
            }
        }
    }

    #pragma unroll
    for (int r = 0; r < NROW; ++r) {
        float v = acc[r];
        #pragma unroll
        for (int o = 16; o; o >>= 1) v += __shfl_down_sync(0xffffffffu, v, o);
        if (lane == 0) sred[warp][r] = v;
    }
    __syncthreads();
    if (t < NROW) {
        float s = 0.f;
        #pragma unroll
        for (int w = 0; w < 8; ++w) s += sred[w][t];
        if      (t < NEC)       out[idx*NEC + t]                = s + b_span[t];
        else if (t < NEC + NRC) g_p1[idx*NRC + (t - NEC)]       = s;
        else                    g_p2[idx*NRC + (t - NEC - NRC)] = s;
    }
}

// -----------------------------------------------------------------------------
// K2: 400 ctx blocks. Pool relation context; 6 ctx dots; gather p1[head] +
// p2[tail] (ready via the K1->K2 graph edge); write relation logits.
// -----------------------------------------------------------------------------
__global__ void __launch_bounds__(256)
spert_relctx_kernel(const float* __restrict__ hid,
                    const int*   __restrict__ rel,
                    const int*   __restrict__ cmask,
                    const float* __restrict__ b_rel,
                    const float* __restrict__ w_rel,
                    float*       __restrict__ out)
{
    __shared__ float sred[8][NRC];
    __shared__ int s_start, s_len;

    const int idx  = blockIdx.x;         // b*R + r
    const int b    = idx / RR;
    const int t    = threadIdx.x;
    const int warp = t >> 5, lane = t & 31;

    // issue the pair-index load early (needed only at the very end)
    const int hi = rel[idx*2 + 0];
    const int ti = rel[idx*2 + 1];

    scan_span(cmask + (size_t)idx * LL, t, warp, lane, &s_start, &s_len);
    const int start = s_start;
    const int len   = s_len;

    float acc[NRC];
    #pragma unroll
    for (int j = 0; j < NRC; ++j) acc[j] = 0.f;

    if (t < H4) {
        const float4* hb = reinterpret_cast<const float4*>(hid + (size_t)b * LL * HH) + t;
        const float4 mx = pool_span(hb, start, len);
        float rv[4] = {mx.x, mx.y, mx.z, mx.w};

        float w24[24];
        const float4* wp = reinterpret_cast<const float4*>(w_rel + 4*t*NRC);
        #pragma unroll
        for (int q = 0; q < 6; ++q)
            *reinterpret_cast<float4*>(w24 + 4*q) = wp[q];
        #pragma unroll
        for (int r = 0; r < 4; ++r)
            #pragma unroll
            for (int j = 0; j < NRC; ++j)
                acc[j] += rv[r] * w24[r*NRC + j];
    }

    #pragma unroll
    for (int j = 0; j < NRC; ++j) {
        float v = acc[j];
        #pragma unroll
        for (int o = 16; o; o >>= 1) v += __shfl_down_sync(0xffffffffu, v, o);
        if (lane == 0) sred[warp][j] = v;
    }
    __syncthreads();
    if (t < NRC) {
        float s = 0.f;
        #pragma unroll
        for (int w = 0; w < 8; ++w) s += sred[w][t];
        out[NENT*NEC + idx*NRC + t] = s
                                    + g_p1[(b*SS + hi)*NRC + t]
                                    + g_p2[(b*SS + ti)*NRC + t]
                                    + b_rel[t];
    }
}

// -----------------------------------------------------------------------------
// kernel_launch: inputs per metadata order:
//   0 hidden_states (f32)  1 entity_masks (i32)  2 relations (i32)
//   3 relation_context_masks (i32)  4 size_emb (f32)
//   5 w_span (f32)  6 b_span (f32)  7 w_rel (f32)  8 b_rel (f32)
// out: 6400 f32 = entity_logits (4000) ++ relation_logits (2400)
// -----------------------------------------------------------------------------
extern "C" void kernel_launch(void* const* d_in, const int* in_sizes, int n_in,
                              void* d_out, int out_size)
{
    const float* hid      = (const float*)d_in[0];
    const int*   emask    = (const int*)  d_in[1];
    const int*   rel      = (const int*)  d_in[2];
    const int*   cmask    = (const int*)  d_in[3];
    const float* size_emb = (const float*)d_in[4];
    const float* w_span   = (const float*)d_in[5];
    const float* b_span   = (const float*)d_in[6];
    const float* w_rel    = (const float*)d_in[7];
    const float* b_rel    = (const float*)d_in[8];
    float* out = (float*)d_out;

    spert_entity_kernel<<<NENT, 256>>>(hid, emask, size_emb,
                                       w_span, b_span, w_rel, out);
    spert_relctx_kernel<<<NREL, 256>>>(hid, rel, cmask, b_rel, w_rel, out);
}

// round 15
// speedup vs baseline: 1.7957x; 1.1333x over previous
#include <cuda_runtime.h>
#include <cuda_bf16.h>

// Problem constants (fixed by the reference)
#define BB  4
#define LL  512
#define HH  768
#define SS  100
#define RR  100
#define EE  25
#define NEC 10              // entity classes
#define NRC 6               // relation classes
#define NEGV (-1e20f)

#define H4       (HH/4)         // 192 float4 lanes per hidden row
#define NENT     (BB*SS)        // 400
#define NREL     (BB*RR)        // 400
#define NROW     (NEC + 2*NRC)  // 22 projection rows per entity block

static __device__ __forceinline__ float4 fmax4(float4 a, float4 b) {
    a.x = fmaxf(a.x, b.x); a.y = fmaxf(a.y, b.y);
    a.z = fmaxf(a.z, b.z); a.w = fmaxf(a.w, b.w);
    return a;
}

// masked max pool over a contiguous span, this thread's float4 lane
static __device__ __forceinline__
float4 pool_span(const float4* __restrict__ hb, int start, int len)
{
    float4 mx = make_float4(NEGV, NEGV, NEGV, NEGV);
    int l = start;
    const int e = start + len;
    for (; l + 4 <= e; l += 4) {
        float4 v0 = hb[(size_t)(l+0) * H4];
        float4 v1 = hb[(size_t)(l+1) * H4];
        float4 v2 = hb[(size_t)(l+2) * H4];
        float4 v3 = hb[(size_t)(l+3) * H4];
        mx = fmax4(mx, fmax4(fmax4(v0, v1), fmax4(v2, v3)));
    }
    for (; l < e; ++l)
        mx = fmax4(mx, hb[(size_t)l * H4]);
    return mx;
}

// contiguous 0/1 span scan: (start,len) via ballot + shared atomics
static __device__ __forceinline__
void scan_span(const int* __restrict__ mrow, int t, int warp, int lane,
               int* s_start, int* s_len)
{
    const int m0 = mrow[t];
    const int m1 = mrow[t + 256];
    if (t == 0) { *s_start = LL; *s_len = 0; }
    __syncthreads();
    unsigned b0 = __ballot_sync(0xffffffffu, m0 != 0);
    unsigned b1 = __ballot_sync(0xffffffffu, m1 != 0);
    if (lane == 0) {
        int cnt = __popc(b0) + __popc(b1);
        if (cnt) {
            int st = b0 ? (warp << 5) + __ffs(b0) - 1
                        : 256 + (warp << 5) + __ffs(b1) - 1;
            atomicMin(s_start, st);
            atomicAdd(s_len, cnt);
        }
    }
    __syncthreads();
}

// graph-safe static scratch
__device__ float g_p1[NENT*NRC];   // head projections per entity
__device__ float g_p2[NENT*NRC];   // tail projections per entity
__device__ float g_pc[NREL*NRC];   // ctx projections per relation

// -----------------------------------------------------------------------------
// K1: 800 blocks — all pooling shares one grid (max L2 concurrency), all dots
// stay in registers.
//   blocks [0,400):   entity — pool + 22 projections -> out, g_p1, g_p2
//   blocks [400,800): ctx    — pool + 6 projections  -> g_pc
// -----------------------------------------------------------------------------
__global__ void __launch_bounds__(256)
spert_main_kernel(const float* __restrict__ hid,
                  const int*   __restrict__ emask,
                  const int*   __restrict__ cmask,
                  const float* __restrict__ size_emb,
                  const float* __restrict__ w_span,
                  const float* __restrict__ b_span,
                  const float* __restrict__ w_rel,
                  float*       __restrict__ out)
{
    __shared__ float sred[8][NROW];
    __shared__ int s_start, s_len;

    const int bid  = blockIdx.x;
    const int t    = threadIdx.x;
    const int warp = t >> 5, lane = t & 31;
    const bool is_ent = (bid < NENT);
    const int idx  = is_ent ? bid : bid - NENT;   // b*N + n
    const int b    = idx / SS;

    scan_span((is_ent ? emask : cmask) + (size_t)idx * LL, t, warp, lane,
              &s_start, &s_len);
    const int start = s_start;
    const int len   = s_len;

    if (is_ent) {
        // ================= ENTITY BLOCK =================
        float acc[NROW];
        #pragma unroll
        for (int r = 0; r < NROW; ++r) acc[r] = 0.f;

        if (t < H4) {
            const float4* hb = reinterpret_cast<const float4*>(hid + (size_t)b * LL * HH) + t;
            const float4 mx = pool_span(hb, start, len);
            float rv[4] = {mx.x, mx.y, mx.z, mx.w};

            // span: w_span rows 4t..4t+3 (40 contiguous floats)
            {
                float w40[40];
                const float4* wp = reinterpret_cast<const float4*>(w_span + 40*t);
                #pragma unroll
                for (int q = 0; q < 10; ++q)
                    *reinterpret_cast<float4*>(w40 + 4*q) = wp[q];
                #pragma unroll
                for (int r = 0; r < 4; ++r)
                    #pragma unroll
                    for (int j = 0; j < NEC; ++j)
                        acc[j] += rv[r] * w40[r*NEC + j];
            }
            // head: w_rel rows 768+4t; tail: rows 1536+4t (24 floats each)
            #pragma unroll
            for (int g = 0; g < 2; ++g) {
                float w24[24];
                const int row0 = (g + 1)*HH + 4*t;
                const float4* wp = reinterpret_cast<const float4*>(w_rel + row0*NRC);
                #pragma unroll
                for (int q = 0; q < 6; ++q)
                    *reinterpret_cast<float4*>(w24 + 4*q) = wp[q];
                const int base = NEC + g*NRC;
                #pragma unroll
                for (int r = 0; r < 4; ++r)
                    #pragma unroll
                    for (int j = 0; j < NRC; ++j)
                        acc[base + j] += rv[r] * w24[r*NRC + j];
            }
        } else if (t < 199) {
            // size-embedding dims d = 4t-768 .. +3 (valid d < 25)
            const int d0 = 4*t - HH;
            const float* se = size_emb + len * EE;
            #pragma unroll
            for (int q = 0; q < 4; ++q) {
                const int d = d0 + q;
                if (d < EE) {
                    const float sv = se[d];
                    #pragma unroll
                    for (int j = 0; j < NEC; ++j)
                        acc[j] += sv * w_span[(HH + d)*NEC + j];
                    #pragma unroll
                    for (int j = 0; j < NRC; ++j) {
                        acc[NEC + j]       += sv * w_rel[(3*HH + d)*NRC + j];
                        acc[NEC + NRC + j] += sv * w_rel[(3*HH + EE + d)*NRC + j];
                    }
                }
            }
        }

        #pragma unroll
        for (int r = 0; r < NROW; ++r) {
            float v = acc[r];
            #pragma unroll
            for (int o = 16; o; o >>= 1) v += __shfl_down_sync(0xffffffffu, v, o);
            if (lane == 0) sred[warp][r] = v;
        }
        __syncthreads();
        if (t < NROW) {
            float s = 0.f;
            #pragma unroll
            for (int w = 0; w < 8; ++w) s += sred[w][t];
            if      (t < NEC)       out[idx*NEC + t]                = s + b_span[t];
            else if (t < NEC + NRC) g_p1[idx*NRC + (t - NEC)]       = s;
            else                    g_p2[idx*NRC + (t - NEC - NRC)] = s;
        }
    } else {
        // ================= CTX BLOCK =================
        float acc[NRC];
        #pragma unroll
        for (int j = 0; j < NRC; ++j) acc[j] = 0.f;

        if (t < H4) {
            const float4* hb = reinterpret_cast<const float4*>(hid + (size_t)b * LL * HH) + t;
            const float4 mx = pool_span(hb, start, len);
            float rv[4] = {mx.x, mx.y, mx.z, mx.w};

            float w24[24];
            const float4* wp = reinterpret_cast<const float4*>(w_rel + 4*t*NRC);
            #pragma unroll
            for (int q = 0; q < 6; ++q)
                *reinterpret_cast<float4*>(w24 + 4*q) = wp[q];
            #pragma unroll
            for (int r = 0; r < 4; ++r)
                #pragma unroll
                for (int j = 0; j < NRC; ++j)
                    acc[j] += rv[r] * w24[r*NRC + j];
        }

        #pragma unroll
        for (int j = 0; j < NRC; ++j) {
            float v = acc[j];
            #pragma unroll
            for (int o = 16; o; o >>= 1) v += __shfl_down_sync(0xffffffffu, v, o);
            if (lane == 0) sred[warp][j] = v;
        }
        __syncthreads();
        if (t < NRC) {
            float s = 0.f;
            #pragma unroll
            for (int w = 0; w < 8; ++w) s += sred[w][t];
            g_pc[idx*NRC + t] = s;
        }
    }
}

// -----------------------------------------------------------------------------
// K2: trivial combine — rel_logits = pc + p1[head] + p2[tail] + bias
// -----------------------------------------------------------------------------
__global__ void __launch_bounds__(256)
spert_combine_kernel(const int*   __restrict__ rel,
                     const float* __restrict__ b_rel,
                     float*       __restrict__ out)
{
    const int i = blockIdx.x * 256 + threadIdx.x;
    if (i < NREL*NRC) {
        const int rid = i / NRC, j = i - rid*NRC;
        const int b   = rid / RR;
        const int hi  = rel[rid*2 + 0];
        const int ti  = rel[rid*2 + 1];
        out[NENT*NEC + i] = g_pc[i]
                          + g_p1[(b*SS + hi)*NRC + j]
                          + g_p2[(b*SS + ti)*NRC + j]
                          + b_rel[j];
    }
}

// -----------------------------------------------------------------------------
// kernel_launch: inputs per metadata order:
//   0 hidden_states (f32)  1 entity_masks (i32)  2 relations (i32)
//   3 relation_context_masks (i32)  4 size_emb (f32)
//   5 w_span (f32)  6 b_span (f32)  7 w_rel (f32)  8 b_rel (f32)
// out: 6400 f32 = entity_logits (4000) ++ relation_logits (2400)
// -----------------------------------------------------------------------------
extern "C" void kernel_launch(void* const* d_in, const int* in_sizes, int n_in,
                              void* d_out, int out_size)
{
    const float* hid      = (const float*)d_in[0];
    const int*   emask    = (const int*)  d_in[1];
    const int*   rel      = (const int*)  d_in[2];
    const int*   cmask    = (const int*)  d_in[3];
    const float* size_emb = (const float*)d_in[4];
    const float* w_span   = (const float*)d_in[5];
    const float* b_span   = (const float*)d_in[6];
    const float* w_rel    = (const float*)d_in[7];
    const float* b_rel    = (const float*)d_in[8];
    float* out = (float*)d_out;

    spert_main_kernel<<<NENT + NREL, 256>>>(hid, emask, cmask, size_emb,
                                            w_span, b_span, w_rel, out);
    spert_combine_kernel<<<(NREL*NRC + 255)/256, 256>>>(rel, b_rel, out);
}